// round 4
// baseline (speedup 1.0000x reference)
#include <cuda_runtime.h>
#include <cuda_bf16.h>
#include <math.h>
#include <stdint.h>

#define Bq 8
#define Cq 256
#define Hq 128
#define Wq 128
#define Pq (Hq*Wq)
#define NHq 8
#define HDq 32
#define NGq (Bq*NHq)

// Scratch (no allocations allowed)
__device__ float g_ix[Bq*NHq*Pq];
__device__ float g_iy[Bq*NHq*Pq];
__device__ float g_V [Bq*Cq*Pq];   // V projection, (B,C,P)
__device__ float g_sum[NGq];
__device__ float g_sq [NGq];
__device__ float g_mean[NGq];
__device__ float g_rstd[NGq];

// ---------------------------------------------------------------- helpers
__device__ __forceinline__ uint32_t smem_u32(const void* p) {
    uint32_t a;
    asm("{ .reg .u64 t; cvta.to.shared.u64 t, %1; cvt.u32.u64 %0, t; }" : "=r"(a) : "l"(p));
    return a;
}

__device__ __forceinline__ uint32_t swz(uint32_t byte) {
    return byte ^ ((byte >> 3) & 0x70);
}

__device__ __forceinline__ void ldsm4(uint32_t* r, uint32_t a) {
    asm volatile("ldmatrix.sync.aligned.m8n8.x4.shared.b16 {%0,%1,%2,%3}, [%4];"
        : "=r"(r[0]), "=r"(r[1]), "=r"(r[2]), "=r"(r[3]) : "r"(a));
}

__device__ __forceinline__ void mma16816(float* d, const uint32_t* a, const uint32_t* b) {
    asm volatile(
        "mma.sync.aligned.m16n8k16.row.col.f32.bf16.bf16.f32 "
        "{%0,%1,%2,%3}, {%4,%5,%6,%7}, {%8,%9}, {%0,%1,%2,%3};"
        : "+f"(d[0]), "+f"(d[1]), "+f"(d[2]), "+f"(d[3])
        : "r"(a[0]), "r"(a[1]), "r"(a[2]), "r"(a[3]), "r"(b[0]), "r"(b[1]));
}

__device__ __forceinline__ uint32_t a_addr(uint32_t base, int m_base, int kb, int lane) {
    int mat = lane >> 3, r = lane & 7;
    int row = m_base + ((mat & 1) << 3) + r;
    int col = kb + ((mat >> 1) << 3);
    return base + swz((uint32_t)(row * 128 + col * 2));
}

__device__ __forceinline__ uint32_t b_addr(uint32_t base, int n_base, int kb, int lane) {
    int mat = lane >> 3, r = lane & 7;
    int row = n_base + ((mat >> 1) << 3) + r;
    int col = kb + ((mat & 1) << 3);
    return base + swz((uint32_t)(row * 128 + col * 2));
}

// ---------------------------------------------------------------- small kernels
__global__ void k_zero() {
    int i = threadIdx.x;
    if (i < NGq) { g_sum[i] = 0.f; g_sq[i] = 0.f; }
}

// Fused dwconv 3x3 -> offset proj -> tanh -> grid coords. Smem-staged version.
// Block: 256 threads handles a 2-row strip (2x128 pixels) of one batch.
__global__ void __launch_bounds__(256) k_offsets(const float* __restrict__ x,
                                                 const float* __restrict__ dw,
                                                 const float* __restrict__ offw,
                                                 const float* __restrict__ offb) {
    __shared__ float xs[2][4][Wq];       // double-buffered 4-row channel strip
    __shared__ float offw_s[Cq*16];      // [c][o], 64B-aligned rows for LDS.128
    __shared__ float dw_s[Cq*9];

    const int tid = threadIdx.x;
    const int px  = tid & 127;
    const int ry  = tid >> 7;            // 0 or 1
    const int b   = blockIdx.y;
    const int r0  = blockIdx.x * 2;

    for (int i = tid; i < Cq*9; i += 256) dw_s[i] = __ldg(dw + i);
#pragma unroll
    for (int o = 0; o < 16; o++) offw_s[tid*16 + o] = __ldg(offw + o*Cq + tid);

    float acc[16];
#pragma unroll
    for (int o = 0; o < 16; o++) acc[o] = __ldg(offb + o);

    const float* xb = x + (size_t)b * Cq * Pq;

    // preload channel 0
    {
        const float* xc = xb;
#pragma unroll
        for (int j = 0; j < 2; j++) {
            int rr = ry + 2*j;
            int gr = r0 - 1 + rr;
            xs[0][rr][px] = (gr >= 0 && gr < Hq) ? xc[gr*Wq + px] : 0.f;
        }
    }
    __syncthreads();

    for (int c = 0; c < Cq; c++) {
        const int buf = c & 1;
        // stencil for pixel (r0+ry, px): buffer rows ry..ry+2, cols px-1..px+1
        float hv = 0.f;
        const float* wv = &dw_s[c*9];
#pragma unroll
        for (int ky = 0; ky < 3; ky++) {
            const float* row = xs[buf][ry + ky];
            float wl = wv[ky*3+0], wc = wv[ky*3+1], wr = wv[ky*3+2];
            if (px > 0)      hv = fmaf(row[px-1], wl, hv);
                             hv = fmaf(row[px  ], wc, hv);
            if (px < Wq-1)   hv = fmaf(row[px+1], wr, hv);
        }
#pragma unroll
        for (int o4 = 0; o4 < 4; o4++) {
            float4 w4 = *(const float4*)&offw_s[c*16 + o4*4];
            acc[o4*4+0] = fmaf(hv, w4.x, acc[o4*4+0]);
            acc[o4*4+1] = fmaf(hv, w4.y, acc[o4*4+1]);
            acc[o4*4+2] = fmaf(hv, w4.z, acc[o4*4+2]);
            acc[o4*4+3] = fmaf(hv, w4.w, acc[o4*4+3]);
        }
        // load next channel into other buffer
        if (c + 1 < Cq) {
            const float* xc = xb + (size_t)(c+1) * Pq;
#pragma unroll
            for (int j = 0; j < 2; j++) {
                int rr = ry + 2*j;
                int gr = r0 - 1 + rr;
                xs[buf^1][rr][px] = (gr >= 0 && gr < Hq) ? xc[gr*Wq + px] : 0.f;
            }
            __syncthreads();
        }
    }

    const int y = r0 + ry;
    const int p = y * Wq + px;
    float gy = -1.f + 2.f * (float)y  / (float)(Hq - 1);
    float gx = -1.f + 2.f * (float)px / (float)(Wq - 1);
#pragma unroll
    for (int hh = 0; hh < NHq; hh++) {
        float dy = tanhf(acc[2*hh  ]) * 0.5f;
        float dx = tanhf(acc[2*hh+1]) * 0.5f;
        float sy = fminf(fmaxf(gy + dy, -1.f), 1.f);
        float sx = fminf(fmaxf(gx + dx, -1.f), 1.f);
        g_iy[(b*NHq + hh)*Pq + p] = (sy + 1.f) * 0.5f * (float)(Hq - 1);
        g_ix[(b*NHq + hh)*Pq + p] = (sx + 1.f) * 0.5f * (float)(Wq - 1);
    }
}

__global__ void k_finalize() {
    int g = threadIdx.x;
    if (g < NGq) {
        float n  = (float)(HDq * Pq);
        float mu = g_sum[g] / n;
        float var = g_sq[g] / n - mu * mu;
        g_mean[g] = mu;
        g_rstd[g] = rsqrtf(var + 1e-5f);
    }
}

__global__ void k_norm(const float* __restrict__ x,
                       const float* __restrict__ gamma,
                       const float* __restrict__ beta,
                       float* __restrict__ out) {
    size_t i = (size_t)blockIdx.x * blockDim.x + threadIdx.x;
    int c = (int)((i / Pq) % Cq);
    int b = (int)(i / ((size_t)Cq * Pq));
    int g = b * NHq + c / HDq;
    float v = out[i];
    out[i] = x[i] + (v - g_mean[g]) * g_rstd[g] * __ldg(gamma + c) + __ldg(beta + c);
}

// ---------------------------------------------------------------- HMMA GEMM
// Out[b][o][p] = sum_c W[o][c] * B[c][p], fp32 via bf16 hi/lo split (3 passes).
// SAMPLE: B[c][p] is bilinearly gathered on the fly from g_V using g_ix/g_iy.
// Block tile 128(o) x 128(p), K-chunks 64. Warps 2(M)x4(N), warp tile 64x32.
#define SMEM_GEMM_BYTES (65536 + 64)

template<bool STATS, bool SAMPLE>
__global__ void __launch_bounds__(256, 2) k_gemm_mma(const float* __restrict__ W,
                                                     const float* __restrict__ In,
                                                     float* __restrict__ Out) {
    extern __shared__ char dsm[];
    const int tid   = threadIdx.x;
    const int lane  = tid & 31;
    const int wid   = tid >> 5;
    const int b     = blockIdx.z;
    const int om    = blockIdx.y * 128;
    const int p0    = blockIdx.x * 128;
    const int mwarp = wid & 1;
    const int nwarp = wid >> 1;

    uint32_t sb = smem_u32(dsm);
    const uint32_t sA_hi = sb;
    const uint32_t sB_hi = sb + 32768;
    char* pA_hi = dsm;
    char* pA_lo = dsm + 16384;
    char* pB_hi = dsm + 32768;
    char* pB_lo = dsm + 49152;
    float* ssum = (float*)(dsm + 65536);
    if (STATS && tid < 8) ssum[tid] = 0.f;

    float acc[4][4][4] = {};
    const float* Inb = In + (size_t)b * Cq * Pq;

    // SAMPLE thread mapping: n = tid&127 (pixel), khalf = (tid>>7)*32 (head half)
    const int bn    = tid & 127;
    const int khalf = (tid >> 7) * 32;

    for (int kc = 0; kc < 4; kc++) {
        const int k0 = kc * 64;
        __syncthreads();

        // --- A tile: 128 rows(m) x 64 cols(k) ---
#pragma unroll
        for (int i = 0; i < 8; i++) {
            int idx4 = tid + i * 256;
            int row  = idx4 >> 4;
            int c4   = (idx4 & 15) * 4;
            float4 v = *(const float4*)(W + (size_t)(om + row) * Cq + k0 + c4);
            __nv_bfloat16 h0 = __float2bfloat16(v.x);
            __nv_bfloat16 h1 = __float2bfloat16(v.y);
            __nv_bfloat16 h2 = __float2bfloat16(v.z);
            __nv_bfloat16 h3 = __float2bfloat16(v.w);
            __nv_bfloat16 l0 = __float2bfloat16(v.x - __bfloat162float(h0));
            __nv_bfloat16 l1 = __float2bfloat16(v.y - __bfloat162float(h1));
            __nv_bfloat16 l2 = __float2bfloat16(v.z - __bfloat162float(h2));
            __nv_bfloat16 l3 = __float2bfloat16(v.w - __bfloat162float(h3));
            uint32_t sw = swz((uint32_t)(row * 128 + c4 * 2));
            uint32_t h01 = (uint32_t)__bfloat16_as_ushort(h0) | ((uint32_t)__bfloat16_as_ushort(h1) << 16);
            uint32_t h23 = (uint32_t)__bfloat16_as_ushort(h2) | ((uint32_t)__bfloat16_as_ushort(h3) << 16);
            uint32_t l01 = (uint32_t)__bfloat16_as_ushort(l0) | ((uint32_t)__bfloat16_as_ushort(l1) << 16);
            uint32_t l23 = (uint32_t)__bfloat16_as_ushort(l2) | ((uint32_t)__bfloat16_as_ushort(l3) << 16);
            *(uint32_t*)(pA_hi + sw)     = h01;
            *(uint32_t*)(pA_hi + sw + 4) = h23;
            *(uint32_t*)(pA_lo + sw)     = l01;
            *(uint32_t*)(pA_lo + sw + 4) = l23;
        }

        // --- B tile: 128 rows(n=p) x 64 cols(k=c) ---
        if (SAMPLE) {
            // this thread: pixel p0+bn, channels k0+khalf .. +31 (one head)
            const int head = kc * 2 + (khalf >> 5);
            const int p    = p0 + bn;
            const int bh   = b * NHq + head;
            float ixv = __ldg(&g_ix[bh*Pq + p]);
            float iyv = __ldg(&g_iy[bh*Pq + p]);
            float x0f = floorf(ixv), y0f = floorf(iyv);
            float wx = ixv - x0f, wy = iyv - y0f;
            int x0i = min(max((int)x0f,     0), Wq - 1);
            int x1i = min(max((int)x0f + 1, 0), Wq - 1);
            int y0i = min(max((int)y0f,     0), Hq - 1);
            int y1i = min(max((int)y0f + 1, 0), Hq - 1);
            float w00 = (1.f-wx)*(1.f-wy), w01 = wx*(1.f-wy);
            float w10 = (1.f-wx)*wy,       w11 = wx*wy;
            int i00 = y0i*Wq + x0i, i01 = y0i*Wq + x1i;
            int i10 = y1i*Wq + x0i, i11 = y1i*Wq + x1i;
            const float* Vc = Inb + (size_t)(k0 + khalf) * Pq;
#pragma unroll 8
            for (int i = 0; i < 32; i++) {
                const float* Vd = Vc + (size_t)i * Pq;
                float v = w00 * __ldg(Vd + i00) + w01 * __ldg(Vd + i01)
                        + w10 * __ldg(Vd + i10) + w11 * __ldg(Vd + i11);
                __nv_bfloat16 h = __float2bfloat16(v);
                __nv_bfloat16 l = __float2bfloat16(v - __bfloat162float(h));
                uint32_t sw = swz((uint32_t)(bn * 128 + (khalf + i) * 2));
                *(__nv_bfloat16*)(pB_hi + sw) = h;
                *(__nv_bfloat16*)(pB_lo + sw) = l;
            }
        } else {
#pragma unroll
            for (int i = 0; i < 32; i++) {
                int idx = tid + i * 256;
                int n = idx & 127;
                int k = idx >> 7;
                float v = __ldg(Inb + (size_t)(k0 + k) * Pq + p0 + n);
                __nv_bfloat16 h = __float2bfloat16(v);
                __nv_bfloat16 l = __float2bfloat16(v - __bfloat162float(h));
                uint32_t sw = swz((uint32_t)(n * 128 + k * 2));
                *(__nv_bfloat16*)(pB_hi + sw) = h;
                *(__nv_bfloat16*)(pB_lo + sw) = l;
            }
        }
        __syncthreads();

        // --- MMA over 4 k16 steps ---
#pragma unroll
        for (int ks = 0; ks < 4; ks++) {
            const int kb = ks * 16;
            uint32_t bh[8], bl[8];
#pragma unroll
            for (int t2 = 0; t2 < 2; t2++) {
                uint32_t ab = b_addr(sB_hi, nwarp * 32 + t2 * 16, kb, lane);
                ldsm4(&bh[t2 * 4], ab);
                ldsm4(&bl[t2 * 4], ab + 16384);
            }
#pragma unroll
            for (int mt = 0; mt < 4; mt++) {
                uint32_t aa = a_addr(sA_hi, mwarp * 64 + mt * 16, kb, lane);
                uint32_t ah[4], al[4];
                ldsm4(ah, aa);
                ldsm4(al, aa + 16384);
#pragma unroll
                for (int nt = 0; nt < 4; nt++) {
                    mma16816(acc[mt][nt], ah, &bh[nt * 2]);
                    mma16816(acc[mt][nt], ah, &bl[nt * 2]);
                    mma16816(acc[mt][nt], al, &bh[nt * 2]);
                }
            }
        }
    }

    // --- Epilogue ---
    const int g  = lane >> 2;
    const int s2 = (lane & 3) * 2;
    float* Ob = Out + (size_t)b * Cq * Pq;
    float slocal[2] = {0.f, 0.f}, qlocal[2] = {0.f, 0.f};

#pragma unroll
    for (int mt = 0; mt < 4; mt++) {
        int o0 = om + mwarp * 64 + mt * 16 + g;
#pragma unroll
        for (int nt = 0; nt < 4; nt++) {
            int p = p0 + nwarp * 32 + nt * 8 + s2;
            float d0 = acc[mt][nt][0], d1 = acc[mt][nt][1];
            float d2 = acc[mt][nt][2], d3 = acc[mt][nt][3];
            *(float2*)(Ob + (size_t)o0 * Pq + p)       = make_float2(d0, d1);
            *(float2*)(Ob + (size_t)(o0 + 8) * Pq + p) = make_float2(d2, d3);
            if (STATS) {
                int j = mt >> 1;
                slocal[j] += d0 + d1 + d2 + d3;
                qlocal[j] += d0*d0 + d1*d1 + d2*d2 + d3*d3;
            }
        }
    }

    if (STATS) {
#pragma unroll
        for (int j = 0; j < 2; j++) {
#pragma unroll
            for (int o = 16; o; o >>= 1) {
                slocal[j] += __shfl_xor_sync(0xFFFFFFFFu, slocal[j], o);
                qlocal[j] += __shfl_xor_sync(0xFFFFFFFFu, qlocal[j], o);
            }
            if (lane == 0) {
                int gidx = mwarp * 2 + j;
                atomicAdd(&ssum[gidx],     slocal[j]);
                atomicAdd(&ssum[4 + gidx], qlocal[j]);
            }
        }
        __syncthreads();
        if (tid < 4) {
            int gg = b * NHq + blockIdx.y * 4 + tid;
            atomicAdd(&g_sum[gg], ssum[tid]);
            atomicAdd(&g_sq[gg],  ssum[4 + tid]);
        }
    }
}

// ---------------------------------------------------------------- launch
extern "C" void kernel_launch(void* const* d_in, const int* in_sizes, int n_in,
                              void* d_out, int out_size) {
    const float* x     = (const float*)d_in[0];
    const float* dw    = (const float*)d_in[1];
    const float* offw  = (const float*)d_in[2];
    const float* offb  = (const float*)d_in[3];
    const float* vw    = (const float*)d_in[4];
    const float* ow    = (const float*)d_in[5];
    const float* gamma = (const float*)d_in[6];
    const float* beta  = (const float*)d_in[7];
    float* out = (float*)d_out;

    cudaFuncSetAttribute(k_gemm_mma<false,false>, cudaFuncAttributeMaxDynamicSharedMemorySize, SMEM_GEMM_BYTES);
    cudaFuncSetAttribute(k_gemm_mma<true,true>,   cudaFuncAttributeMaxDynamicSharedMemorySize, SMEM_GEMM_BYTES);

    float* gV = nullptr; cudaGetSymbolAddress((void**)&gV, g_V);

    k_zero<<<1, 64>>>();
    k_offsets<<<dim3(Hq/2, Bq), 256>>>(x, dw, offw, offb);

    // V projection: g_V = vw @ x
    k_gemm_mma<false,false><<<dim3(Pq/128, Cq/128, Bq), 256, SMEM_GEMM_BYTES>>>(vw, x, gV);
    // O projection with fused bilinear gather + groupnorm stats, into d_out
    k_gemm_mma<true,true><<<dim3(Pq/128, Cq/128, Bq), 256, SMEM_GEMM_BYTES>>>(ow, gV, out);
    k_finalize<<<1, 64>>>();
    k_norm<<<(Bq*Cq*Pq)/256, 256>>>(x, gamma, beta, out);
}